// round 2
// baseline (speedup 1.0000x reference)
#include <cuda_runtime.h>
#include <cuda_bf16.h>
#include <cstdint>

// Problem constants (fixed by the dataset)
#define N_NODES 50000
#define IN_DIM  256
#define OUT_DIM 128          // D

// Scratch: XW1, XW2 intermediates. __device__ globals (no runtime allocation).
// NOTE: never passed as host-side kernel args — device code references them
// directly (passing the symbol from host code was the round-1 bug).
__device__ float g_xw1[(size_t)N_NODES * OUT_DIM];
__device__ float g_xw2[(size_t)N_NODES * OUT_DIM];

// ---------------------------------------------------------------------------
// Vector reduction: 16B atomic add (sm_90+). One op instead of 4 scalar REDGs.
// ---------------------------------------------------------------------------
__device__ __forceinline__ void red_add_v4(float* p, float x, float y, float z, float w) {
#if __CUDA_ARCH__ >= 900
    asm volatile("red.global.add.v4.f32 [%0], {%1, %2, %3, %4};"
                 :: "l"(p), "f"(x), "f"(y), "f"(z), "f"(w)
                 : "memory");
#else
    atomicAdd(p + 0, x);
    atomicAdd(p + 1, y);
    atomicAdd(p + 2, z);
    atomicAdd(p + 3, w);
#endif
}

// ---------------------------------------------------------------------------
// Zero the scratch arrays and the output accumulator.
// ---------------------------------------------------------------------------
__global__ void zero_kernel(float* __restrict__ out, int total_f4) {
    const float4 z = make_float4(0.f, 0.f, 0.f, 0.f);
    int stride = gridDim.x * blockDim.x;
    for (int i = blockIdx.x * blockDim.x + threadIdx.x; i < total_f4; i += stride) {
        reinterpret_cast<float4*>(g_xw1)[i] = z;
        reinterpret_cast<float4*>(g_xw2)[i] = z;
        reinterpret_cast<float4*>(out)[i]   = z;
    }
}

// ---------------------------------------------------------------------------
// Feature SpMM (fused for both relations):
//   g_xw1[row] += val * W1[col];  g_xw2[row] += val * W2[col]
// One warp per nonzero; lane l owns columns 4l..4l+3.
// W rows are 512B; both W's (256KB total) stay cache-hot.
// ---------------------------------------------------------------------------
__global__ void feat_kernel(const int* __restrict__ frow,
                            const int* __restrict__ fcol,
                            const float* __restrict__ fval,
                            const float* __restrict__ W1,
                            const float* __restrict__ W2,
                            int nnz) {
    int gwarp = (blockIdx.x * blockDim.x + threadIdx.x) >> 5;
    int lane  = threadIdx.x & 31;
    if (gwarp >= nnz) return;

    int   r = frow[gwarp];
    int   c = fcol[gwarp];
    float v = fval[gwarp];

    float4 w1 = reinterpret_cast<const float4*>(W1 + (size_t)c * OUT_DIM)[lane];
    float4 w2 = reinterpret_cast<const float4*>(W2 + (size_t)c * OUT_DIM)[lane];

    float* p1 = g_xw1 + (size_t)r * OUT_DIM + lane * 4;
    float* p2 = g_xw2 + (size_t)r * OUT_DIM + lane * 4;
    red_add_v4(p1, v * w1.x, v * w1.y, v * w1.z, v * w1.w);
    red_add_v4(p2, v * w2.x, v * w2.y, v * w2.z, v * w2.w);
}

// ---------------------------------------------------------------------------
// Fused adjacency SpMM for BOTH relations:
//   edge e < nnz1 : out[a1_row[e]] += a1_val[e] * g_xw1[a1_col[e]]
//   edge e >= nnz1: out[a2_row[e']] += a2_val[e'] * g_xw2[a2_col[e']]
// One warp per edge; gathers a 512B row from L2-resident scratch, red.v4 out.
// ---------------------------------------------------------------------------
__global__ void adj_kernel(const int* __restrict__ a1row,
                           const int* __restrict__ a1col,
                           const float* __restrict__ a1val,
                           const int* __restrict__ a2row,
                           const int* __restrict__ a2col,
                           const float* __restrict__ a2val,
                           float* __restrict__ out,
                           int nnz1, int nnz_total) {
    int e    = (blockIdx.x * blockDim.x + threadIdx.x) >> 5;
    int lane = threadIdx.x & 31;
    if (e >= nnz_total) return;

    int r, c;
    float v;
    const float* H;
    if (e < nnz1) {
        r = a1row[e]; c = a1col[e]; v = a1val[e];
        H = g_xw1;
    } else {
        int e2 = e - nnz1;
        r = a2row[e2]; c = a2col[e2]; v = a2val[e2];
        H = g_xw2;
    }

    float4 h = reinterpret_cast<const float4*>(H + (size_t)c * OUT_DIM)[lane];
    float* p = out + (size_t)r * OUT_DIM + lane * 4;
    red_add_v4(p, v * h.x, v * h.y, v * h.z, v * h.w);
}

// ---------------------------------------------------------------------------
// In-place ReLU on the accumulated output.
// ---------------------------------------------------------------------------
__global__ void relu_kernel(float* __restrict__ out, int total_f4) {
    int stride = gridDim.x * blockDim.x;
    for (int i = blockIdx.x * blockDim.x + threadIdx.x; i < total_f4; i += stride) {
        float4 v = reinterpret_cast<float4*>(out)[i];
        v.x = fmaxf(v.x, 0.f);
        v.y = fmaxf(v.y, 0.f);
        v.z = fmaxf(v.z, 0.f);
        v.w = fmaxf(v.w, 0.f);
        reinterpret_cast<float4*>(out)[i] = v;
    }
}

// ---------------------------------------------------------------------------
// Launch. Input order (metadata): feat_row, feat_col, feat_vals,
// adj1_row, adj1_col, adj1_vals, adj2_row, adj2_col, adj2_vals, W1, W2, n_nodes
// ---------------------------------------------------------------------------
extern "C" void kernel_launch(void* const* d_in, const int* in_sizes, int n_in,
                              void* d_out, int out_size) {
    const int*   feat_row = (const int*)  d_in[0];
    const int*   feat_col = (const int*)  d_in[1];
    const float* feat_val = (const float*)d_in[2];
    const int*   a1_row   = (const int*)  d_in[3];
    const int*   a1_col   = (const int*)  d_in[4];
    const float* a1_val   = (const float*)d_in[5];
    const int*   a2_row   = (const int*)  d_in[6];
    const int*   a2_col   = (const int*)  d_in[7];
    const float* a2_val   = (const float*)d_in[8];
    const float* W1       = (const float*)d_in[9];
    const float* W2       = (const float*)d_in[10];

    float* out = (float*)d_out;

    const int nnz_feat  = in_sizes[0];
    const int nnz_a1    = in_sizes[3];
    const int nnz_a2    = in_sizes[6];
    const int nnz_adj   = nnz_a1 + nnz_a2;
    const int total_f4  = out_size / 4;   // = N_NODES * OUT_DIM / 4

    // 1) zero scratch + output
    zero_kernel<<<2048, 256>>>(out, total_f4);

    // 2) feature SpMM for both relations (1 warp / nnz, 8 warps / block)
    feat_kernel<<<(nnz_feat + 7) / 8, 256>>>(feat_row, feat_col, feat_val,
                                             W1, W2, nnz_feat);

    // 3) fused adjacency SpMM for both relations, accumulating x1+x2 into out
    adj_kernel<<<(nnz_adj + 7) / 8, 256>>>(a1_row, a1_col, a1_val,
                                           a2_row, a2_col, a2_val,
                                           out, nnz_a1, nnz_adj);

    // 4) ReLU in place
    relu_kernel<<<2048, 256>>>(out, total_f4);
}